// round 9
// baseline (speedup 1.0000x reference)
#include <cuda_runtime.h>
#include <cuda_bf16.h>
#include <math.h>
#include <stdint.h>

#define Nn 20000
#define F_INn 256
#define HIDn 256
#define EMBn 128
#define HEADSn 8
#define NE 160000
#define NEG_SLOPE 0.2f

// ---------------- scratch (device globals; no cudaMalloc allowed) ----------
__device__ float g_bufA[(size_t)Nn * 1024];
__device__ float g_bufB[(size_t)Nn * 1024];
__device__ float g_dinv[Nn];
__device__ int   g_cnt[Nn];
__device__ int   g_cursor[Nn];
__device__ int   g_rowptr[Nn + 1];
__device__ int   g_col[NE];
__device__ float g_as[Nn * HEADSn];
__device__ float g_ad[Nn * HEADSn];
__device__ float g_m[Nn * HEADSn];
__device__ float g_s[Nn * HEADSn];
__device__ float g_w[Nn];
__device__ float g_partial[128];
__device__ float g_total;
__device__ int   g_is64;

// Split-precision weights (hi/lo bf16), [K,N] row-major (same as inputs)
#define WOFF_W1  0
#define WOFF_W2  65536
#define WOFF_W3  131072
#define WOFF_WG  163840
#define WOFF_WH1 294912
#define WTOTAL   557056
__device__ __nv_bfloat16 g_whi[WTOTAL];
__device__ __nv_bfloat16 g_wlo[WTOTAL];

// ---------------- helpers ---------------------------------------------------
__device__ __forceinline__ float lrelu(float x) { return x > 0.f ? x : NEG_SLOPE * x; }

__device__ __forceinline__ int load_idx(const void* ei, long long i) {
    if (g_is64) return (int)((const long long*)ei)[i];
    return ((const int*)ei)[i];
}

__global__ void k_detect(const int* __restrict__ ei32) {
    if (threadIdx.x == 0) {
        int is64 = 1;
        for (int i = 1; i < 128; i += 2)
            if (ei32[i] != 0) { is64 = 0; break; }
        g_is64 = is64;
    }
}

// ---------------- CSR build -------------------------------------------------
__global__ void k_zero_counts() {
    int i = blockIdx.x * blockDim.x + threadIdx.x;
    if (i < Nn) { g_cnt[i] = 0; g_cursor[i] = 0; }
}

__global__ void k_count(const void* __restrict__ ei) {
    int e = blockIdx.x * blockDim.x + threadIdx.x;
    if (e < NE) atomicAdd(&g_cnt[load_idx(ei, (long long)NE + e)], 1);
}

__global__ void k_dinv() {
    int i = blockIdx.x * blockDim.x + threadIdx.x;
    if (i < Nn) g_dinv[i] = rsqrtf((float)(g_cnt[i] + 1));
}

__global__ void k_scan() {
    __shared__ int tmp[1024];
    __shared__ int s_base;
    int tid = threadIdx.x;
    if (tid == 0) { s_base = 0; g_rowptr[0] = 0; }
    __syncthreads();
    for (int start = 0; start < Nn; start += 1024) {
        int i = start + tid;
        int v = (i < Nn) ? g_cnt[i] : 0;
        tmp[tid] = v;
        __syncthreads();
        for (int d = 1; d < 1024; d <<= 1) {
            int t = (tid >= d) ? tmp[tid - d] : 0;
            __syncthreads();
            tmp[tid] += t;
            __syncthreads();
        }
        int b = s_base;
        if (i < Nn) g_rowptr[i + 1] = b + tmp[tid];
        __syncthreads();
        if (tid == 1023) s_base = b + tmp[1023];
        __syncthreads();
    }
}

__global__ void k_fill(const void* __restrict__ ei) {
    int e = blockIdx.x * blockDim.x + threadIdx.x;
    if (e < NE) {
        int s = load_idx(ei, e);
        int d = load_idx(ei, (long long)NE + e);
        int p = g_rowptr[d] + atomicAdd(&g_cursor[d], 1);
        g_col[p] = s;
    }
}

// ---------------- weight split: fp32 -> bf16 hi + bf16 lo -------------------
__global__ void k_split(const float* __restrict__ src,
                        __nv_bfloat16* __restrict__ hi,
                        __nv_bfloat16* __restrict__ lo, int n) {
    int i = blockIdx.x * blockDim.x + threadIdx.x;
    if (i < n) {
        float v = src[i];
        __nv_bfloat16 h = __float2bfloat16_rn(v);
        float r = v - __bfloat162float(h);
        hi[i] = h;
        lo[i] = __float2bfloat16_rn(r);
    }
}

// ---------------- tensor-core GEMM (bf16 split, 3 MMA products) -------------
// C[M,N] = A[M,K](fp32) @ B[K,N](pre-split bf16 hi/lo), optional bias + relu.
// BM=128 BN=128 BK=32, 256 threads = 8 warps (4m x 2n), warp tile 32x64.
#define BM 128
#define BN 128
#define BK 32
#define ASTR 40    // bf16 elems per A smem row (32 + 8 pad)
#define BSTR 136   // bf16 elems per B smem row (128 + 8 pad)

__device__ __forceinline__ uint32_t smem_u32(const void* p) {
    return (uint32_t)__cvta_generic_to_shared(p);
}
__device__ __forceinline__ void ldsm4(uint32_t* r, uint32_t a) {
    asm volatile("ldmatrix.sync.aligned.m8n8.x4.shared.b16 {%0,%1,%2,%3}, [%4];"
                 : "=r"(r[0]), "=r"(r[1]), "=r"(r[2]), "=r"(r[3]) : "r"(a));
}
__device__ __forceinline__ void ldsm4t(uint32_t* r, uint32_t a) {
    asm volatile("ldmatrix.sync.aligned.m8n8.x4.trans.shared.b16 {%0,%1,%2,%3}, [%4];"
                 : "=r"(r[0]), "=r"(r[1]), "=r"(r[2]), "=r"(r[3]) : "r"(a));
}
__device__ __forceinline__ void mma16816(float* c, const uint32_t* a, const uint32_t* b) {
    asm volatile(
        "mma.sync.aligned.m16n8k16.row.col.f32.bf16.bf16.f32 "
        "{%0,%1,%2,%3}, {%4,%5,%6,%7}, {%8,%9}, {%0,%1,%2,%3};"
        : "+f"(c[0]), "+f"(c[1]), "+f"(c[2]), "+f"(c[3])
        : "r"(a[0]), "r"(a[1]), "r"(a[2]), "r"(a[3]), "r"(b[0]), "r"(b[1]));
}

__global__ void __launch_bounds__(256, 1) k_gemm(
    const float* __restrict__ A,
    const __nv_bfloat16* __restrict__ Bhi, const __nv_bfloat16* __restrict__ Blo,
    const float* __restrict__ bias, float* __restrict__ C,
    int M, int N, int K, int relu)
{
    __shared__ __align__(16) __nv_bfloat16 sAh[BM * ASTR];
    __shared__ __align__(16) __nv_bfloat16 sAl[BM * ASTR];
    __shared__ __align__(16) __nv_bfloat16 sBh[BK * BSTR];
    __shared__ __align__(16) __nv_bfloat16 sBl[BK * BSTR];

    int tid = threadIdx.x;
    int warp = tid >> 5, lane = tid & 31;
    int wm = warp >> 1, wn = warp & 1;
    int m0 = blockIdx.y * BM, n0 = blockIdx.x * BN;

    float acc[2][8][4];
#pragma unroll
    for (int i = 0; i < 2; i++)
#pragma unroll
        for (int j = 0; j < 8; j++)
#pragma unroll
            for (int k = 0; k < 4; k++) acc[i][j][k] = 0.f;

    float4 aReg[4];
    uint4 bRegH[2], bRegL[2];

    // A loader: 1024 float4 per tile (128x32 fp32), 4 per thread
    int arow[4], acol4[4];
#pragma unroll
    for (int r = 0; r < 4; r++) {
        int idx = r * 256 + tid;
        arow[r] = idx >> 3;
        acol4[r] = (idx & 7) << 2;
    }
    // B loader: 32x128 bf16 (hi & lo) = 4096 elems, 2 passes x 8 per thread
    int brow[2], bn8[2];
#pragma unroll
    for (int r = 0; r < 2; r++) {
        int idx = r * 256 + tid;
        brow[r] = idx >> 4;
        bn8[r] = (idx & 15) << 3;
    }

    int iters = K / BK;

    // prefetch first tile
    {
        int kk = 0;
#pragma unroll
        for (int r = 0; r < 4; r++) {
            int gm = m0 + arow[r];
            aReg[r] = (gm < M)
                ? *reinterpret_cast<const float4*>(A + (size_t)gm * K + kk + acol4[r])
                : make_float4(0.f, 0.f, 0.f, 0.f);
        }
#pragma unroll
        for (int r = 0; r < 2; r++) {
            const __nv_bfloat16* ph = Bhi + (size_t)(kk + brow[r]) * N + n0 + bn8[r];
            const __nv_bfloat16* pl = Blo + (size_t)(kk + brow[r]) * N + n0 + bn8[r];
            bRegH[r] = *reinterpret_cast<const uint4*>(ph);
            bRegL[r] = *reinterpret_cast<const uint4*>(pl);
        }
    }

    for (int it = 0; it < iters; ++it) {
        // stage regs -> smem (A converted to hi/lo)
#pragma unroll
        for (int r = 0; r < 4; r++) {
            float4 v = aReg[r];
            __nv_bfloat162 h01 = __floats2bfloat162_rn(v.x, v.y);
            __nv_bfloat162 h23 = __floats2bfloat162_rn(v.z, v.w);
            float rx = v.x - __bfloat162float(__low2bfloat16(h01));
            float ry = v.y - __bfloat162float(__high2bfloat16(h01));
            float rz = v.z - __bfloat162float(__low2bfloat16(h23));
            float rw = v.w - __bfloat162float(__high2bfloat16(h23));
            __nv_bfloat162 l01 = __floats2bfloat162_rn(rx, ry);
            __nv_bfloat162 l23 = __floats2bfloat162_rn(rz, rw);
            uint2 uh, ul;
            uh.x = *reinterpret_cast<uint32_t*>(&h01);
            uh.y = *reinterpret_cast<uint32_t*>(&h23);
            ul.x = *reinterpret_cast<uint32_t*>(&l01);
            ul.y = *reinterpret_cast<uint32_t*>(&l23);
            int off = arow[r] * ASTR + acol4[r];
            *reinterpret_cast<uint2*>(&sAh[off]) = uh;
            *reinterpret_cast<uint2*>(&sAl[off]) = ul;
        }
#pragma unroll
        for (int r = 0; r < 2; r++) {
            int off = brow[r] * BSTR + bn8[r];
            *reinterpret_cast<uint4*>(&sBh[off]) = bRegH[r];
            *reinterpret_cast<uint4*>(&sBl[off]) = bRegL[r];
        }
        __syncthreads();

        // prefetch next tile
        if (it + 1 < iters) {
            int kk = (it + 1) * BK;
#pragma unroll
            for (int r = 0; r < 4; r++) {
                int gm = m0 + arow[r];
                aReg[r] = (gm < M)
                    ? *reinterpret_cast<const float4*>(A + (size_t)gm * K + kk + acol4[r])
                    : make_float4(0.f, 0.f, 0.f, 0.f);
            }
#pragma unroll
            for (int r = 0; r < 2; r++) {
                const __nv_bfloat16* ph = Bhi + (size_t)(kk + brow[r]) * N + n0 + bn8[r];
                const __nv_bfloat16* pl = Blo + (size_t)(kk + brow[r]) * N + n0 + bn8[r];
                bRegH[r] = *reinterpret_cast<const uint4*>(ph);
                bRegL[r] = *reinterpret_cast<const uint4*>(pl);
            }
        }

        // compute: 2 k16 steps
#pragma unroll
        for (int ks = 0; ks < 2; ks++) {
            uint32_t ah[2][4], al[2][4];
#pragma unroll
            for (int mt = 0; mt < 2; mt++) {
                int row = wm * 32 + mt * 16 + (lane & 15);
                int ko = ks * 16 + (lane >> 4) * 8;
                ldsm4(ah[mt], smem_u32(&sAh[row * ASTR + ko]));
                ldsm4(al[mt], smem_u32(&sAl[row * ASTR + ko]));
            }
            uint32_t bh[4][4], bl[4][4];
#pragma unroll
            for (int bt = 0; bt < 4; bt++) {
                int krow = ks * 16 + (lane & 15);
                int ncol = wn * 64 + bt * 16 + (lane >> 4) * 8;
                ldsm4t(bh[bt], smem_u32(&sBh[krow * BSTR + ncol]));
                ldsm4t(bl[bt], smem_u32(&sBl[krow * BSTR + ncol]));
            }
#pragma unroll
            for (int mt = 0; mt < 2; mt++)
#pragma unroll
                for (int nt = 0; nt < 8; nt++) {
                    const uint32_t* bph = &bh[nt >> 1][(nt & 1) * 2];
                    const uint32_t* bpl = &bl[nt >> 1][(nt & 1) * 2];
                    mma16816(acc[mt][nt], ah[mt], bph);  // hi*hi
                    mma16816(acc[mt][nt], al[mt], bph);  // lo*hi
                    mma16816(acc[mt][nt], ah[mt], bpl);  // hi*lo
                }
        }
        __syncthreads();
    }

    // epilogue (register -> global)
    int gid = lane >> 2, tig = lane & 3;
#pragma unroll
    for (int mt = 0; mt < 2; mt++) {
#pragma unroll
        for (int nt = 0; nt < 8; nt++) {
            int col = n0 + wn * 64 + nt * 8 + tig * 2;
            float bx = 0.f, by = 0.f;
            if (bias) { bx = bias[col]; by = bias[col + 1]; }
            int row0 = m0 + wm * 32 + mt * 16 + gid;
            float2 v0, v1;
            v0.x = acc[mt][nt][0] + bx; v0.y = acc[mt][nt][1] + by;
            v1.x = acc[mt][nt][2] + bx; v1.y = acc[mt][nt][3] + by;
            if (relu) {
                v0.x = fmaxf(v0.x, 0.f); v0.y = fmaxf(v0.y, 0.f);
                v1.x = fmaxf(v1.x, 0.f); v1.y = fmaxf(v1.y, 0.f);
            }
            if (row0 < M)
                *reinterpret_cast<float2*>(C + (size_t)row0 * N + col) = v0;
            if (row0 + 8 < M)
                *reinterpret_cast<float2*>(C + (size_t)(row0 + 8) * N + col) = v1;
        }
    }
}

// ---------------- GCN aggregation: warp per node, float4 --------------------
template <int F>
__global__ void k_gcn_agg(const float* __restrict__ t,
                          const float* __restrict__ bias,
                          float* __restrict__ out)
{
    int node = blockIdx.x * (blockDim.x >> 5) + (threadIdx.x >> 5);
    if (node >= Nn) return;
    int lane = threadIdx.x & 31;
    constexpr int J = F / 128;
    float4 acc[J];
    float di = g_dinv[node];
    const float4* selfrow = reinterpret_cast<const float4*>(t + (size_t)node * F);
#pragma unroll
    for (int j = 0; j < J; j++) {
        float4 v = selfrow[lane + 32 * j];
        acc[j] = make_float4(di * v.x, di * v.y, di * v.z, di * v.w);
    }
    int beg = g_rowptr[node], end = g_rowptr[node + 1];
    for (int p = beg; p < end; ++p) {
        int s = g_col[p];
        float c = g_dinv[s];
        const float4* row = reinterpret_cast<const float4*>(t + (size_t)s * F);
#pragma unroll
        for (int j = 0; j < J; j++) {
            float4 v = row[lane + 32 * j];
            acc[j].x = fmaf(c, v.x, acc[j].x);
            acc[j].y = fmaf(c, v.y, acc[j].y);
            acc[j].z = fmaf(c, v.z, acc[j].z);
            acc[j].w = fmaf(c, v.w, acc[j].w);
        }
    }
    const float4* b4 = reinterpret_cast<const float4*>(bias);
    float4* o4 = reinterpret_cast<float4*>(out + (size_t)node * F);
#pragma unroll
    for (int j = 0; j < J; j++) {
        float4 bb = b4[lane + 32 * j];
        float4 v;
        v.x = fmaxf(di * acc[j].x + bb.x, 0.f);
        v.y = fmaxf(di * acc[j].y + bb.y, 0.f);
        v.z = fmaxf(di * acc[j].z + bb.z, 0.f);
        v.w = fmaxf(di * acc[j].w + bb.w, 0.f);
        o4[lane + 32 * j] = v;
    }
}

// ---------------- GAT: per-node attention scores (float4) -------------------
__global__ void k_gat_scores(const float* __restrict__ hg,
                             const float* __restrict__ att_src,
                             const float* __restrict__ att_dst)
{
    int node = blockIdx.x * (blockDim.x >> 5) + (threadIdx.x >> 5);
    if (node >= Nn) return;
    int lane = threadIdx.x & 31;
    const float4* base = reinterpret_cast<const float4*>(hg + (size_t)node * (HEADSn * EMBn));
    const float4* as4 = reinterpret_cast<const float4*>(att_src);
    const float4* ad4 = reinterpret_cast<const float4*>(att_dst);
#pragma unroll
    for (int h = 0; h < HEADSn; ++h) {
        float4 xv = base[h * 32 + lane];
        float4 sv = as4[h * 32 + lane];
        float4 dv = ad4[h * 32 + lane];
        float vs = xv.x * sv.x + xv.y * sv.y + xv.z * sv.z + xv.w * sv.w;
        float vd = xv.x * dv.x + xv.y * dv.y + xv.z * dv.z + xv.w * dv.w;
#pragma unroll
        for (int o = 16; o > 0; o >>= 1) {
            vs += __shfl_down_sync(0xffffffffu, vs, o);
            vd += __shfl_down_sync(0xffffffffu, vd, o);
        }
        if (lane == 0) {
            g_as[node * HEADSn + h] = vs;
            g_ad[node * HEADSn + h] = vd;
        }
    }
}

// ---------------- GAT: online max/sum per (node, head) ----------------------
__global__ void k_gat_stats() {
    int t = blockIdx.x * blockDim.x + threadIdx.x;
    if (t >= Nn * HEADSn) return;
    int node = t >> 3;
    int h = t & 7;
    float ad = g_ad[t];
    float m = lrelu(g_as[t] + ad);
    float s = 1.0f;
    int beg = g_rowptr[node], end = g_rowptr[node + 1];
    for (int p = beg; p < end; ++p) {
        int src = g_col[p];
        float e = lrelu(g_as[src * HEADSn + h] + ad);
        if (e > m) { s = s * __expf(m - e) + 1.f; m = e; }
        else       { s += __expf(e - m); }
    }
    g_m[t] = m; g_s[t] = s;
}

// ---------------- GAT: weighted aggregation, warp per (node, head), float4 --
__global__ void k_gat_agg(const float* __restrict__ hg,
                          const float* __restrict__ bg,
                          float* __restrict__ out)
{
    int node = blockIdx.x;
    int h = threadIdx.x >> 5;
    int lane = threadIdx.x & 31;
    int t = node * HEADSn + h;
    float m = g_m[t];
    float sinv = 1.0f / g_s[t];
    float ad = g_ad[t];
    float aself = __expf(lrelu(g_as[t] + ad) - m) * sinv;
    const float4* srow = reinterpret_cast<const float4*>(
        hg + (size_t)node * (HEADSn * EMBn) + h * EMBn);
    float4 v = srow[lane];
    float4 acc = make_float4(aself * v.x, aself * v.y, aself * v.z, aself * v.w);
    int beg = g_rowptr[node], end = g_rowptr[node + 1];
    for (int p = beg; p < end; ++p) {
        int src = g_col[p];
        float alpha = __expf(lrelu(g_as[src * HEADSn + h] + ad) - m) * sinv;
        const float4* row = reinterpret_cast<const float4*>(
            hg + (size_t)src * (HEADSn * EMBn) + h * EMBn);
        float4 w = row[lane];
        acc.x = fmaf(alpha, w.x, acc.x);
        acc.y = fmaf(alpha, w.y, acc.y);
        acc.z = fmaf(alpha, w.z, acc.z);
        acc.w = fmaf(alpha, w.w, acc.w);
    }
    const float4* bg4 = reinterpret_cast<const float4*>(bg + h * EMBn);
    float4 bb = bg4[lane];
    acc.x += bb.x; acc.y += bb.y; acc.z += bb.z; acc.w += bb.w;
    float4* o4 = reinterpret_cast<float4*>(
        out + (size_t)node * (HEADSn * EMBn) + h * EMBn);
    o4[lane] = acc;
}

// ---------------- head: logits -> sigmoid ------------------------------------
__global__ void k_logits(const float* __restrict__ z,
                         const float* __restrict__ Wh2,
                         const float* __restrict__ bh2)
{
    int node = blockIdx.x * (blockDim.x >> 5) + (threadIdx.x >> 5);
    if (node >= Nn) return;
    int lane = threadIdx.x & 31;
    const float4* row = reinterpret_cast<const float4*>(z + (size_t)node * HIDn);
    const float4* w4 = reinterpret_cast<const float4*>(Wh2);
    float v = 0.f;
#pragma unroll
    for (int j = 0; j < HIDn / 128; j++) {
        float4 a = row[lane + 32 * j];
        float4 b = w4[lane + 32 * j];
        v += a.x * b.x + a.y * b.y + a.z * b.z + a.w * b.w;
    }
#pragma unroll
    for (int o = 16; o > 0; o >>= 1) v += __shfl_down_sync(0xffffffffu, v, o);
    if (lane == 0) {
        float logit = v + bh2[0];
        g_w[node] = 1.0f / (1.0f + __expf(-logit));
    }
}

// ---------------- softmax over all N (deterministic two-level) --------------
__global__ void k_exp_partial() {
    __shared__ float red[256];
    int i = blockIdx.x * 256 + threadIdx.x;
    float e = 0.f;
    if (i < Nn) { e = __expf(g_w[i]); g_w[i] = e; }
    red[threadIdx.x] = e;
    __syncthreads();
    for (int o = 128; o > 0; o >>= 1) {
        if (threadIdx.x < o) red[threadIdx.x] += red[threadIdx.x + o];
        __syncthreads();
    }
    if (threadIdx.x == 0) g_partial[blockIdx.x] = red[0];
}

__global__ void k_sum_partials(int nb) {
    __shared__ float red[128];
    float v = ((int)threadIdx.x < nb) ? g_partial[threadIdx.x] : 0.f;
    red[threadIdx.x] = v;
    __syncthreads();
    for (int o = 64; o > 0; o >>= 1) {
        if (threadIdx.x < o) red[threadIdx.x] += red[threadIdx.x + o];
        __syncthreads();
    }
    if (threadIdx.x == 0) g_total = red[0];
}

__global__ void k_normalize(float* __restrict__ out) {
    int i = blockIdx.x * blockDim.x + threadIdx.x;
    if (i < Nn) out[i] = g_w[i] / g_total;
}

// ---------------- launch ------------------------------------------------------
extern "C" void kernel_launch(void* const* d_in, const int* in_sizes, int n_in,
                              void* d_out, int out_size)
{
    const float* x        = (const float*)d_in[0];
    const void*  ei       = d_in[1];
    const float* W1       = (const float*)d_in[2];
    const float* b1       = (const float*)d_in[3];
    const float* W2       = (const float*)d_in[4];
    const float* b2       = (const float*)d_in[5];
    const float* W3       = (const float*)d_in[6];
    const float* b3       = (const float*)d_in[7];
    const float* Wg       = (const float*)d_in[8];
    const float* att_src  = (const float*)d_in[9];
    const float* att_dst  = (const float*)d_in[10];
    const float* bg       = (const float*)d_in[11];
    const float* Wh1      = (const float*)d_in[12];
    const float* bh1      = (const float*)d_in[13];
    const float* Wh2      = (const float*)d_in[14];
    const float* bh2      = (const float*)d_in[15];
    float* out = (float*)d_out;

    float *bufA, *bufB;
    __nv_bfloat16 *whi, *wlo;
    cudaGetSymbolAddress((void**)&bufA, g_bufA);
    cudaGetSymbolAddress((void**)&bufB, g_bufB);
    cudaGetSymbolAddress((void**)&whi, g_whi);
    cudaGetSymbolAddress((void**)&wlo, g_wlo);

    // Graph/CSR prep
    k_detect<<<1, 32>>>((const int*)ei);
    k_zero_counts<<<(Nn + 255) / 256, 256>>>();
    k_count<<<(NE + 255) / 256, 256>>>(ei);
    k_dinv<<<(Nn + 255) / 256, 256>>>();
    k_scan<<<1, 1024>>>();
    k_fill<<<(NE + 255) / 256, 256>>>(ei);

    // Weight splits (hi/lo bf16)
    k_split<<<(65536 + 255) / 256, 256>>>(W1, whi + WOFF_W1, wlo + WOFF_W1, 65536);
    k_split<<<(65536 + 255) / 256, 256>>>(W2, whi + WOFF_W2, wlo + WOFF_W2, 65536);
    k_split<<<(32768 + 255) / 256, 256>>>(W3, whi + WOFF_W3, wlo + WOFF_W3, 32768);
    k_split<<<(131072 + 255) / 256, 256>>>(Wg, whi + WOFF_WG, wlo + WOFF_WG, 131072);
    k_split<<<(262144 + 255) / 256, 256>>>(Wh1, whi + WOFF_WH1, wlo + WOFF_WH1, 262144);

    dim3 blk(256);
    int mtiles = (Nn + BM - 1) / BM;
    // GCN 1: [N,256]@[256,256]
    { dim3 g(HIDn / BN, mtiles);
      k_gemm<<<g, blk>>>(x, whi + WOFF_W1, wlo + WOFF_W1, nullptr, bufA, Nn, HIDn, F_INn, 0); }
    k_gcn_agg<HIDn><<<(Nn + 7) / 8, 256>>>(bufA, b1, bufB);
    // GCN 2
    { dim3 g(HIDn / BN, mtiles);
      k_gemm<<<g, blk>>>(bufB, whi + WOFF_W2, wlo + WOFF_W2, nullptr, bufA, Nn, HIDn, HIDn, 0); }
    k_gcn_agg<HIDn><<<(Nn + 7) / 8, 256>>>(bufA, b2, bufB);
    // GCN 3 (256 -> 128)
    { dim3 g(EMBn / BN, mtiles);
      k_gemm<<<g, blk>>>(bufB, whi + WOFF_W3, wlo + WOFF_W3, nullptr, bufA, Nn, EMBn, HIDn, 0); }
    k_gcn_agg<EMBn><<<(Nn + 7) / 8, 256>>>(bufA, b3, bufB);
    // GAT projection (128 -> 1024)
    { dim3 g((HEADSn * EMBn) / BN, mtiles);
      k_gemm<<<g, blk>>>(bufB, whi + WOFF_WG, wlo + WOFF_WG, nullptr, bufA, Nn, HEADSn * EMBn, EMBn, 0); }
    k_gat_scores<<<(Nn + 7) / 8, 256>>>(bufA, att_src, att_dst);
    k_gat_stats<<<(Nn * HEADSn + 255) / 256, 256>>>();
    k_gat_agg<<<Nn, 256>>>(bufA, bg, bufB);
    // Head MLP (1024 -> 256) + relu
    { dim3 g(HIDn / BN, mtiles);
      k_gemm<<<g, blk>>>(bufB, whi + WOFF_WH1, wlo + WOFF_WH1, bh1, bufA, Nn, HIDn, HEADSn * EMBn, 1); }
    k_logits<<<(Nn + 7) / 8, 256>>>(bufA, Wh2, bh2);
    int nb = (Nn + 255) / 256;
    k_exp_partial<<<nb, 256>>>();
    k_sum_partials<<<1, 128>>>(nb);
    k_normalize<<<nb, 256>>>(out);
}

// round 10
// speedup vs baseline: 1.0065x; 1.0065x over previous
#include <cuda_runtime.h>
#include <cuda_bf16.h>
#include <math.h>
#include <stdint.h>

#define Nn 20000
#define F_INn 256
#define HIDn 256
#define EMBn 128
#define HEADSn 8
#define NE 160000
#define NEG_SLOPE 0.2f

// ---------------- scratch (device globals; no cudaMalloc allowed) ----------
__device__ float g_bufA[(size_t)Nn * 1024];
__device__ float g_bufB[(size_t)Nn * 1024];
__device__ float g_dinv[Nn];
__device__ int   g_cnt[Nn];
__device__ int   g_cursor[Nn];
__device__ int   g_rowptr[Nn + 1];
__device__ int   g_col[NE];
__device__ float g_as[Nn * HEADSn];
__device__ float g_ad[Nn * HEADSn];
__device__ float g_m[Nn * HEADSn];
__device__ float g_s[Nn * HEADSn];
__device__ float g_w[Nn];
__device__ float g_partial[128];
__device__ float g_total;
__device__ int   g_is64;

// Split-precision weights (hi/lo bf16), [K,N] row-major (same as inputs)
#define WOFF_W1  0
#define WOFF_W2  65536
#define WOFF_W3  131072
#define WOFF_WG  163840
#define WOFF_WH1 294912
#define WTOTAL   557056
__device__ __nv_bfloat16 g_whi[WTOTAL];
__device__ __nv_bfloat16 g_wlo[WTOTAL];

// ---------------- helpers ---------------------------------------------------
__device__ __forceinline__ float lrelu(float x) { return x > 0.f ? x : NEG_SLOPE * x; }

__device__ __forceinline__ int load_idx(const void* ei, long long i) {
    if (g_is64) return (int)((const long long*)ei)[i];
    return ((const int*)ei)[i];
}

__global__ void k_detect(const int* __restrict__ ei32) {
    if (threadIdx.x == 0) {
        int is64 = 1;
        for (int i = 1; i < 128; i += 2)
            if (ei32[i] != 0) { is64 = 0; break; }
        g_is64 = is64;
    }
}

// ---------------- CSR build -------------------------------------------------
__global__ void k_zero_counts() {
    int i = blockIdx.x * blockDim.x + threadIdx.x;
    if (i < Nn) { g_cnt[i] = 0; g_cursor[i] = 0; }
}

__global__ void k_count(const void* __restrict__ ei) {
    int e = blockIdx.x * blockDim.x + threadIdx.x;
    if (e < NE) atomicAdd(&g_cnt[load_idx(ei, (long long)NE + e)], 1);
}

__global__ void k_dinv() {
    int i = blockIdx.x * blockDim.x + threadIdx.x;
    if (i < Nn) g_dinv[i] = rsqrtf((float)(g_cnt[i] + 1));
}

__global__ void k_scan() {
    __shared__ int tmp[1024];
    __shared__ int s_base;
    int tid = threadIdx.x;
    if (tid == 0) { s_base = 0; g_rowptr[0] = 0; }
    __syncthreads();
    for (int start = 0; start < Nn; start += 1024) {
        int i = start + tid;
        int v = (i < Nn) ? g_cnt[i] : 0;
        tmp[tid] = v;
        __syncthreads();
        for (int d = 1; d < 1024; d <<= 1) {
            int t = (tid >= d) ? tmp[tid - d] : 0;
            __syncthreads();
            tmp[tid] += t;
            __syncthreads();
        }
        int b = s_base;
        if (i < Nn) g_rowptr[i + 1] = b + tmp[tid];
        __syncthreads();
        if (tid == 1023) s_base = b + tmp[1023];
        __syncthreads();
    }
}

__global__ void k_fill(const void* __restrict__ ei) {
    int e = blockIdx.x * blockDim.x + threadIdx.x;
    if (e < NE) {
        int s = load_idx(ei, e);
        int d = load_idx(ei, (long long)NE + e);
        int p = g_rowptr[d] + atomicAdd(&g_cursor[d], 1);
        g_col[p] = s;
    }
}

// ---------------- weight split: fp32 -> bf16 hi + bf16 lo -------------------
__global__ void k_split(const float* __restrict__ src,
                        __nv_bfloat16* __restrict__ hi,
                        __nv_bfloat16* __restrict__ lo, int n) {
    int i = blockIdx.x * blockDim.x + threadIdx.x;
    if (i < n) {
        float v = src[i];
        __nv_bfloat16 h = __float2bfloat16_rn(v);
        float r = v - __bfloat162float(h);
        hi[i] = h;
        lo[i] = __float2bfloat16_rn(r);
    }
}

// ---------------- tensor-core GEMM (bf16 split, 3 MMA products) -------------
// C[M,N] = A[M,K](fp32) @ B[K,N](pre-split bf16 hi/lo), optional bias + relu.
// BM=128 BN=128 BK=32, 256 threads = 8 warps (4m x 2n), warp tile 32x64.
#define BM 128
#define BN 128
#define BK 32
#define ASTR 40    // bf16 elems per A smem row (32 + 8 pad)
#define BSTR 136   // bf16 elems per B smem row (128 + 8 pad)

__device__ __forceinline__ uint32_t smem_u32(const void* p) {
    return (uint32_t)__cvta_generic_to_shared(p);
}
__device__ __forceinline__ void ldsm4(uint32_t* r, uint32_t a) {
    asm volatile("ldmatrix.sync.aligned.m8n8.x4.shared.b16 {%0,%1,%2,%3}, [%4];"
                 : "=r"(r[0]), "=r"(r[1]), "=r"(r[2]), "=r"(r[3]) : "r"(a));
}
__device__ __forceinline__ void ldsm4t(uint32_t* r, uint32_t a) {
    asm volatile("ldmatrix.sync.aligned.m8n8.x4.trans.shared.b16 {%0,%1,%2,%3}, [%4];"
                 : "=r"(r[0]), "=r"(r[1]), "=r"(r[2]), "=r"(r[3]) : "r"(a));
}
__device__ __forceinline__ void mma16816(float* c, const uint32_t* a, const uint32_t* b) {
    asm volatile(
        "mma.sync.aligned.m16n8k16.row.col.f32.bf16.bf16.f32 "
        "{%0,%1,%2,%3}, {%4,%5,%6,%7}, {%8,%9}, {%0,%1,%2,%3};"
        : "+f"(c[0]), "+f"(c[1]), "+f"(c[2]), "+f"(c[3])
        : "r"(a[0]), "r"(a[1]), "r"(a[2]), "r"(a[3]), "r"(b[0]), "r"(b[1]));
}

__global__ void __launch_bounds__(256, 1) k_gemm(
    const float* __restrict__ A,
    const __nv_bfloat16* __restrict__ Bhi, const __nv_bfloat16* __restrict__ Blo,
    const float* __restrict__ bias, float* __restrict__ C,
    int M, int N, int K, int relu)
{
    __shared__ __align__(16) __nv_bfloat16 sAh[BM * ASTR];
    __shared__ __align__(16) __nv_bfloat16 sAl[BM * ASTR];
    __shared__ __align__(16) __nv_bfloat16 sBh[BK * BSTR];
    __shared__ __align__(16) __nv_bfloat16 sBl[BK * BSTR];

    int tid = threadIdx.x;
    int warp = tid >> 5, lane = tid & 31;
    int wm = warp >> 1, wn = warp & 1;
    int m0 = blockIdx.y * BM, n0 = blockIdx.x * BN;

    float acc[2][8][4];
#pragma unroll
    for (int i = 0; i < 2; i++)
#pragma unroll
        for (int j = 0; j < 8; j++)
#pragma unroll
            for (int k = 0; k < 4; k++) acc[i][j][k] = 0.f;

    float4 aReg[4];
    uint4 bRegH[2], bRegL[2];

    // A loader: 1024 float4 per tile (128x32 fp32), 4 per thread
    int arow[4], acol4[4];
#pragma unroll
    for (int r = 0; r < 4; r++) {
        int idx = r * 256 + tid;
        arow[r] = idx >> 3;
        acol4[r] = (idx & 7) << 2;
    }
    // B loader: 32x128 bf16 (hi & lo) = 4096 elems, 2 passes x 8 per thread
    int brow[2], bn8[2];
#pragma unroll
    for (int r = 0; r < 2; r++) {
        int idx = r * 256 + tid;
        brow[r] = idx >> 4;
        bn8[r] = (idx & 15) << 3;
    }

    int iters = K / BK;

    // prefetch first tile
    {
        int kk = 0;
#pragma unroll
        for (int r = 0; r < 4; r++) {
            int gm = m0 + arow[r];
            aReg[r] = (gm < M)
                ? *reinterpret_cast<const float4*>(A + (size_t)gm * K + kk + acol4[r])
                : make_float4(0.f, 0.f, 0.f, 0.f);
        }
#pragma unroll
        for (int r = 0; r < 2; r++) {
            const __nv_bfloat16* ph = Bhi + (size_t)(kk + brow[r]) * N + n0 + bn8[r];
            const __nv_bfloat16* pl = Blo + (size_t)(kk + brow[r]) * N + n0 + bn8[r];
            bRegH[r] = *reinterpret_cast<const uint4*>(ph);
            bRegL[r] = *reinterpret_cast<const uint4*>(pl);
        }
    }

    for (int it = 0; it < iters; ++it) {
        // stage regs -> smem (A converted to hi/lo)
#pragma unroll
        for (int r = 0; r < 4; r++) {
            float4 v = aReg[r];
            __nv_bfloat162 h01 = __floats2bfloat162_rn(v.x, v.y);
            __nv_bfloat162 h23 = __floats2bfloat162_rn(v.z, v.w);
            float rx = v.x - __bfloat162float(__low2bfloat16(h01));
            float ry = v.y - __bfloat162float(__high2bfloat16(h01));
            float rz = v.z - __bfloat162float(__low2bfloat16(h23));
            float rw = v.w - __bfloat162float(__high2bfloat16(h23));
            __nv_bfloat162 l01 = __floats2bfloat162_rn(rx, ry);
            __nv_bfloat162 l23 = __floats2bfloat162_rn(rz, rw);
            uint2 uh, ul;
            uh.x = *reinterpret_cast<uint32_t*>(&h01);
            uh.y = *reinterpret_cast<uint32_t*>(&h23);
            ul.x = *reinterpret_cast<uint32_t*>(&l01);
            ul.y = *reinterpret_cast<uint32_t*>(&l23);
            int off = arow[r] * ASTR + acol4[r];
            *reinterpret_cast<uint2*>(&sAh[off]) = uh;
            *reinterpret_cast<uint2*>(&sAl[off]) = ul;
        }
#pragma unroll
        for (int r = 0; r < 2; r++) {
            int off = brow[r] * BSTR + bn8[r];
            *reinterpret_cast<uint4*>(&sBh[off]) = bRegH[r];
            *reinterpret_cast<uint4*>(&sBl[off]) = bRegL[r];
        }
        __syncthreads();

        // prefetch next tile
        if (it + 1 < iters) {
            int kk = (it + 1) * BK;
#pragma unroll
            for (int r = 0; r < 4; r++) {
                int gm = m0 + arow[r];
                aReg[r] = (gm < M)
                    ? *reinterpret_cast<const float4*>(A + (size_t)gm * K + kk + acol4[r])
                    : make_float4(0.f, 0.f, 0.f, 0.f);
            }
#pragma unroll
            for (int r = 0; r < 2; r++) {
                const __nv_bfloat16* ph = Bhi + (size_t)(kk + brow[r]) * N + n0 + bn8[r];
                const __nv_bfloat16* pl = Blo + (size_t)(kk + brow[r]) * N + n0 + bn8[r];
                bRegH[r] = *reinterpret_cast<const uint4*>(ph);
                bRegL[r] = *reinterpret_cast<const uint4*>(pl);
            }
        }

        // compute: 2 k16 steps
#pragma unroll
        for (int ks = 0; ks < 2; ks++) {
            uint32_t ah[2][4], al[2][4];
#pragma unroll
            for (int mt = 0; mt < 2; mt++) {
                int row = wm * 32 + mt * 16 + (lane & 15);
                int ko = ks * 16 + (lane >> 4) * 8;
                ldsm4(ah[mt], smem_u32(&sAh[row * ASTR + ko]));
                ldsm4(al[mt], smem_u32(&sAl[row * ASTR + ko]));
            }
            uint32_t bh[4][4], bl[4][4];
#pragma unroll
            for (int bt = 0; bt < 4; bt++) {
                int krow = ks * 16 + (lane & 15);
                int ncol = wn * 64 + bt * 16 + (lane >> 4) * 8;
                ldsm4t(bh[bt], smem_u32(&sBh[krow * BSTR + ncol]));
                ldsm4t(bl[bt], smem_u32(&sBl[krow * BSTR + ncol]));
            }
#pragma unroll
            for (int mt = 0; mt < 2; mt++)
#pragma unroll
                for (int nt = 0; nt < 8; nt++) {
                    const uint32_t* bph = &bh[nt >> 1][(nt & 1) * 2];
                    const uint32_t* bpl = &bl[nt >> 1][(nt & 1) * 2];
                    mma16816(acc[mt][nt], ah[mt], bph);  // hi*hi
                    mma16816(acc[mt][nt], al[mt], bph);  // lo*hi
                    mma16816(acc[mt][nt], ah[mt], bpl);  // hi*lo
                }
        }
        __syncthreads();
    }

    // epilogue (register -> global)
    int gid = lane >> 2, tig = lane & 3;
#pragma unroll
    for (int mt = 0; mt < 2; mt++) {
#pragma unroll
        for (int nt = 0; nt < 8; nt++) {
            int col = n0 + wn * 64 + nt * 8 + tig * 2;
            float bx = 0.f, by = 0.f;
            if (bias) { bx = bias[col]; by = bias[col + 1]; }
            int row0 = m0 + wm * 32 + mt * 16 + gid;
            float2 v0, v1;
            v0.x = acc[mt][nt][0] + bx; v0.y = acc[mt][nt][1] + by;
            v1.x = acc[mt][nt][2] + bx; v1.y = acc[mt][nt][3] + by;
            if (relu) {
                v0.x = fmaxf(v0.x, 0.f); v0.y = fmaxf(v0.y, 0.f);
                v1.x = fmaxf(v1.x, 0.f); v1.y = fmaxf(v1.y, 0.f);
            }
            if (row0 < M)
                *reinterpret_cast<float2*>(C + (size_t)row0 * N + col) = v0;
            if (row0 + 8 < M)
                *reinterpret_cast<float2*>(C + (size_t)(row0 + 8) * N + col) = v1;
        }
    }
}

// ---------------- GCN aggregation: warp per node, float4 --------------------
template <int F>
__global__ void k_gcn_agg(const float* __restrict__ t,
                          const float* __restrict__ bias,
                          float* __restrict__ out)
{
    int node = blockIdx.x * (blockDim.x >> 5) + (threadIdx.x >> 5);
    if (node >= Nn) return;
    int lane = threadIdx.x & 31;
    constexpr int J = F / 128;
    float4 acc[J];
    float di = g_dinv[node];
    const float4* selfrow = reinterpret_cast<const float4*>(t + (size_t)node * F);
#pragma unroll
    for (int j = 0; j < J; j++) {
        float4 v = selfrow[lane + 32 * j];
        acc[j] = make_float4(di * v.x, di * v.y, di * v.z, di * v.w);
    }
    int beg = g_rowptr[node], end = g_rowptr[node + 1];
    for (int p = beg; p < end; ++p) {
        int s = g_col[p];
        float c = g_dinv[s];
        const float4* row = reinterpret_cast<const float4*>(t + (size_t)s * F);
#pragma unroll
        for (int j = 0; j < J; j++) {
            float4 v = row[lane + 32 * j];
            acc[j].x = fmaf(c, v.x, acc[j].x);
            acc[j].y = fmaf(c, v.y, acc[j].y);
            acc[j].z = fmaf(c, v.z, acc[j].z);
            acc[j].w = fmaf(c, v.w, acc[j].w);
        }
    }
    const float4* b4 = reinterpret_cast<const float4*>(bias);
    float4* o4 = reinterpret_cast<float4*>(out + (size_t)node * F);
#pragma unroll
    for (int j = 0; j < J; j++) {
        float4 bb = b4[lane + 32 * j];
        float4 v;
        v.x = fmaxf(di * acc[j].x + bb.x, 0.f);
        v.y = fmaxf(di * acc[j].y + bb.y, 0.f);
        v.z = fmaxf(di * acc[j].z + bb.z, 0.f);
        v.w = fmaxf(di * acc[j].w + bb.w, 0.f);
        o4[lane + 32 * j] = v;
    }
}

// ---------------- GAT: per-node attention scores (float4) -------------------
__global__ void k_gat_scores(const float* __restrict__ hg,
                             const float* __restrict__ att_src,
                             const float* __restrict__ att_dst)
{
    int node = blockIdx.x * (blockDim.x >> 5) + (threadIdx.x >> 5);
    if (node >= Nn) return;
    int lane = threadIdx.x & 31;
    const float4* base = reinterpret_cast<const float4*>(hg + (size_t)node * (HEADSn * EMBn));
    const float4* as4 = reinterpret_cast<const float4*>(att_src);
    const float4* ad4 = reinterpret_cast<const float4*>(att_dst);
#pragma unroll
    for (int h = 0; h < HEADSn; ++h) {
        float4 xv = base[h * 32 + lane];
        float4 sv = as4[h * 32 + lane];
        float4 dv = ad4[h * 32 + lane];
        float vs = xv.x * sv.x + xv.y * sv.y + xv.z * sv.z + xv.w * sv.w;
        float vd = xv.x * dv.x + xv.y * dv.y + xv.z * dv.z + xv.w * dv.w;
#pragma unroll
        for (int o = 16; o > 0; o >>= 1) {
            vs += __shfl_down_sync(0xffffffffu, vs, o);
            vd += __shfl_down_sync(0xffffffffu, vd, o);
        }
        if (lane == 0) {
            g_as[node * HEADSn + h] = vs;
            g_ad[node * HEADSn + h] = vd;
        }
    }
}

// ---------------- GAT: online max/sum per (node, head) ----------------------
__global__ void k_gat_stats() {
    int t = blockIdx.x * blockDim.x + threadIdx.x;
    if (t >= Nn * HEADSn) return;
    int node = t >> 3;
    int h = t & 7;
    float ad = g_ad[t];
    float m = lrelu(g_as[t] + ad);
    float s = 1.0f;
    int beg = g_rowptr[node], end = g_rowptr[node + 1];
    for (int p = beg; p < end; ++p) {
        int src = g_col[p];
        float e = lrelu(g_as[src * HEADSn + h] + ad);
        if (e > m) { s = s * __expf(m - e) + 1.f; m = e; }
        else       { s += __expf(e - m); }
    }
    g_m[t] = m; g_s[t] = s;
}

// ---------------- GAT: weighted aggregation, warp per (node, head), float4 --
__global__ void k_gat_agg(const float* __restrict__ hg,
                          const float* __restrict__ bg,
                          float* __restrict__ out)
{
    int node = blockIdx.x;
    int h = threadIdx.x >> 5;
    int lane = threadIdx.x & 31;
    int t = node * HEADSn + h;
    float m = g_m[t];
    float sinv = 1.0f / g_s[t];
    float ad = g_ad[t];
    float aself = __expf(lrelu(g_as[t] + ad) - m) * sinv;
    const float4* srow = reinterpret_cast<const float4*>(
        hg + (size_t)node * (HEADSn * EMBn) + h * EMBn);
    float4 v = srow[lane];
    float4 acc = make_float4(aself * v.x, aself * v.y, aself * v.z, aself * v.w);
    int beg = g_rowptr[node], end = g_rowptr[node + 1];
    for (int p = beg; p < end; ++p) {
        int src = g_col[p];
        float alpha = __expf(lrelu(g_as[src * HEADSn + h] + ad) - m) * sinv;
        const float4* row = reinterpret_cast<const float4*>(
            hg + (size_t)src * (HEADSn * EMBn) + h * EMBn);
        float4 w = row[lane];
        acc.x = fmaf(alpha, w.x, acc.x);
        acc.y = fmaf(alpha, w.y, acc.y);
        acc.z = fmaf(alpha, w.z, acc.z);
        acc.w = fmaf(alpha, w.w, acc.w);
    }
    const float4* bg4 = reinterpret_cast<const float4*>(bg + h * EMBn);
    float4 bb = bg4[lane];
    acc.x += bb.x; acc.y += bb.y; acc.z += bb.z; acc.w += bb.w;
    float4* o4 = reinterpret_cast<float4*>(
        out + (size_t)node * (HEADSn * EMBn) + h * EMBn);
    o4[lane] = acc;
}

// ---------------- head: logits -> sigmoid ------------------------------------
__global__ void k_logits(const float* __restrict__ z,
                         const float* __restrict__ Wh2,
                         const float* __restrict__ bh2)
{
    int node = blockIdx.x * (blockDim.x >> 5) + (threadIdx.x >> 5);
    if (node >= Nn) return;
    int lane = threadIdx.x & 31;
    const float4* row = reinterpret_cast<const float4*>(z + (size_t)node * HIDn);
    const float4* w4 = reinterpret_cast<const float4*>(Wh2);
    float v = 0.f;
#pragma unroll
    for (int j = 0; j < HIDn / 128; j++) {
        float4 a = row[lane + 32 * j];
        float4 b = w4[lane + 32 * j];
        v += a.x * b.x + a.y * b.y + a.z * b.z + a.w * b.w;
    }
#pragma unroll
    for (int o = 16; o > 0; o >>= 1) v += __shfl_down_sync(0xffffffffu, v, o);
    if (lane == 0) {
        float logit = v + bh2[0];
        g_w[node] = 1.0f / (1.0f + __expf(-logit));
    }
}

// ---------------- softmax over all N (deterministic two-level) --------------
__global__ void k_exp_partial() {
    __shared__ float red[256];
    int i = blockIdx.x * 256 + threadIdx.x;
    float e = 0.f;
    if (i < Nn) { e = __expf(g_w[i]); g_w[i] = e; }
    red[threadIdx.x] = e;
    __syncthreads();
    for (int o = 128; o > 0; o >>= 1) {
        if (threadIdx.x < o) red[threadIdx.x] += red[threadIdx.x + o];
        __syncthreads();
    }
    if (threadIdx.x == 0) g_partial[blockIdx.x] = red[0];
}

__global__ void k_sum_partials(int nb) {
    __shared__ float red[128];
    float v = ((int)threadIdx.x < nb) ? g_partial[threadIdx.x] : 0.f;
    red[threadIdx.x] = v;
    __syncthreads();
    for (int o = 64; o > 0; o >>= 1) {
        if (threadIdx.x < o) red[threadIdx.x] += red[threadIdx.x + o];
        __syncthreads();
    }
    if (threadIdx.x == 0) g_total = red[0];
}

__global__ void k_normalize(float* __restrict__ out) {
    int i = blockIdx.x * blockDim.x + threadIdx.x;
    if (i < Nn) out[i] = g_w[i] / g_total;
}

// ---------------- launch ------------------------------------------------------
extern "C" void kernel_launch(void* const* d_in, const int* in_sizes, int n_in,
                              void* d_out, int out_size)
{
    const float* x        = (const float*)d_in[0];
    const void*  ei       = d_in[1];
    const float* W1       = (const float*)d_in[2];
    const float* b1       = (const float*)d_in[3];
    const float* W2       = (const float*)d_in[4];
    const float* b2       = (const float*)d_in[5];
    const float* W3       = (const float*)d_in[6];
    const float* b3       = (const float*)d_in[7];
    const float* Wg       = (const float*)d_in[8];
    const float* att_src  = (const float*)d_in[9];
    const float* att_dst  = (const float*)d_in[10];
    const float* bg       = (const float*)d_in[11];
    const float* Wh1      = (const float*)d_in[12];
    const float* bh1      = (const float*)d_in[13];
    const float* Wh2      = (const float*)d_in[14];
    const float* bh2      = (const float*)d_in[15];
    float* out = (float*)d_out;

    float *bufA, *bufB;
    __nv_bfloat16 *whi, *wlo;
    cudaGetSymbolAddress((void**)&bufA, g_bufA);
    cudaGetSymbolAddress((void**)&bufB, g_bufB);
    cudaGetSymbolAddress((void**)&whi, g_whi);
    cudaGetSymbolAddress((void**)&wlo, g_wlo);

    // Graph/CSR prep
    k_detect<<<1, 32>>>((const int*)ei);
    k_zero_counts<<<(Nn + 255) / 256, 256>>>();
    k_count<<<(NE + 255) / 256, 256>>>(ei);
    k_dinv<<<(Nn + 255) / 256, 256>>>();
    k_scan<<<1, 1024>>>();
    k_fill<<<(NE + 255) / 256, 256>>>(ei);

    // Weight splits (hi/lo bf16)
    k_split<<<(65536 + 255) / 256, 256>>>(W1, whi + WOFF_W1, wlo + WOFF_W1, 65536);
    k_split<<<(65536 + 255) / 256, 256>>>(W2, whi + WOFF_W2, wlo + WOFF_W2, 65536);
    k_split<<<(32768 + 255) / 256, 256>>>(W3, whi + WOFF_W3, wlo + WOFF_W3, 32768);
    k_split<<<(131072 + 255) / 256, 256>>>(Wg, whi + WOFF_WG, wlo + WOFF_WG, 131072);
    k_split<<<(262144 + 255) / 256, 256>>>(Wh1, whi + WOFF_WH1, wlo + WOFF_WH1, 262144);

    dim3 blk(256);
    int mtiles = (Nn + BM - 1) / BM;
    // GCN 1: [N,256]@[256,256]
    { dim3 g(HIDn / BN, mtiles);
      k_gemm<<<g, blk>>>(x, whi + WOFF_W1, wlo + WOFF_W1, nullptr, bufA, Nn, HIDn, F_INn, 0); }
    k_gcn_agg<HIDn><<<(Nn + 7) / 8, 256>>>(bufA, b1, bufB);
    // GCN 2
    { dim3 g(HIDn / BN, mtiles);
      k_gemm<<<g, blk>>>(bufB, whi + WOFF_W2, wlo + WOFF_W2, nullptr, bufA, Nn, HIDn, HIDn, 0); }
    k_gcn_agg<HIDn><<<(Nn + 7) / 8, 256>>>(bufA, b2, bufB);
    // GCN 3 (256 -> 128)
    { dim3 g(EMBn / BN, mtiles);
      k_gemm<<<g, blk>>>(bufB, whi + WOFF_W3, wlo + WOFF_W3, nullptr, bufA, Nn, EMBn, HIDn, 0); }
    k_gcn_agg<EMBn><<<(Nn + 7) / 8, 256>>>(bufA, b3, bufB);
    // GAT projection (128 -> 1024)
    { dim3 g((HEADSn * EMBn) / BN, mtiles);
      k_gemm<<<g, blk>>>(bufB, whi + WOFF_WG, wlo + WOFF_WG, nullptr, bufA, Nn, HEADSn * EMBn, EMBn, 0); }
    k_gat_scores<<<(Nn + 7) / 8, 256>>>(bufA, att_src, att_dst);
    k_gat_stats<<<(Nn * HEADSn + 255) / 256, 256>>>();
    k_gat_agg<<<Nn, 256>>>(bufA, bg, bufB);
    // Head MLP (1024 -> 256) + relu
    { dim3 g(HIDn / BN, mtiles);
      k_gemm<<<g, blk>>>(bufB, whi + WOFF_WH1, wlo + WOFF_WH1, bh1, bufA, Nn, HIDn, HEADSn * EMBn, 1); }
    k_logits<<<(Nn + 7) / 8, 256>>>(bufA, Wh2, bh2);
    int nb = (Nn + 255) / 256;
    k_exp_partial<<<nb, 256>>>();
    k_sum_partials<<<1, 128>>>(nb);
    k_normalize<<<nb, 256>>>(out);
}